// round 6
// baseline (speedup 1.0000x reference)
#include <cuda_runtime.h>
#include <math.h>
#include <stdint.h>

#define Hh   12
#define Nn   768
#define C1d  384
#define C2d  128
#define PROJ_DIM 1152
#define FA_DIM   2112

#define SCALAR_W 0.14433756729740643f
#define POINT_W  0.13608276348795434f
#define W2D      0.5773502691896258f

// ---------------- scratch ----------------
__device__ float d_wcat[PROJ_DIM * C1d];
__device__ float d_bcat[PROJ_DIM];
__device__ float d_proj[Nn * PROJ_DIM];
__device__ float d_qcat[Nn * 384];
__device__ float d_kT[Hh * 29 * Nn];
__device__ float d_vcat[Nn * 480];
__device__ float d_lgsp[Nn * Hh * Nn];
__device__ float d_attn[Hh * Nn * Nn];
__device__ float d_rpg[Nn * 288];
__device__ float d_fa[Nn * FA_DIM];
__device__ float d_part[4 * Nn * 384];

// ---------------- tf32 helpers ----------------
__device__ __forceinline__ unsigned f2tf32(float x) {
    unsigned r;
    asm("cvt.rna.tf32.f32 %0, %1;" : "=r"(r) : "f"(x));
    return r;
}

#define MMA_TF32(ac, A0, A1, A2, A3, B0, B1)                                   \
    asm volatile(                                                              \
        "mma.sync.aligned.m16n8k8.row.col.f32.tf32.tf32.f32 "                  \
        "{%0,%1,%2,%3},{%4,%5,%6,%7},{%8,%9},{%0,%1,%2,%3};"                   \
        : "+f"(ac[0]), "+f"(ac[1]), "+f"(ac[2]), "+f"(ac[3])                   \
        : "r"(A0), "r"(A1), "r"(A2), "r"(A3), "r"(B0), "r"(B1))

// ---------------- K0: concat proj weights ----------------
__global__ void concat_w_kernel(const float* __restrict__ wqs, const float* __restrict__ wkvs,
                                const float* __restrict__ wqp, const float* __restrict__ wkvp,
                                const float* __restrict__ bqs, const float* __restrict__ bkvs,
                                const float* __restrict__ bqp, const float* __restrict__ bkvp) {
    int idx = blockIdx.x * blockDim.x + threadIdx.x;
    int stride = gridDim.x * blockDim.x;
    for (int o = idx; o < PROJ_DIM; o += stride) {
        float v;
        if (o < 192)      v = bqs[o];
        else if (o < 576) v = bkvs[o - 192];
        else if (o < 720) v = bqp[o - 576];
        else              v = bkvp[o - 720];
        d_bcat[o] = v;
    }
    const int total = PROJ_DIM * C1d;
    for (int t = idx; t < total; t += stride) {
        int o = t / C1d, k = t % C1d;
        float v;
        if (o < 192)      v = wqs[o * C1d + k];
        else if (o < 576) v = wkvs[(o - 192) * C1d + k];
        else if (o < 720) v = wqp[(o - 576) * C1d + k];
        else              v = wkvp[(o - 720) * C1d + k];
        d_wcat[t] = v;
    }
}

// ---------------- generic split-tf32 GEMM: C = X[M,K]@W[O,K]^T (+bias) ----------------
// grid (O/64, M/64, Z); 256 threads. Near-fp32 precision via 3-term split.
__global__ __launch_bounds__(256) void gemm_tf3_kernel(
        const float* __restrict__ X, int ldx, long long zsx,
        const float* __restrict__ W, int ldw, long long zsw,
        const float* __restrict__ bias, float* __restrict__ C, int ldc, long long zsc,
        int Klen) {
    __shared__ float xh[64][20], xl[64][20], wh[64][20], wl[64][20];
    const int z = blockIdx.z;
    X += (size_t)z * zsx;
    W += (size_t)z * zsw;
    float* Cp = C + (size_t)z * zsc;
    const int m0 = blockIdx.y * 64, o0 = blockIdx.x * 64;
    const int tid = threadIdx.x;
    const int warp = tid >> 5, lane = tid & 31, g = lane >> 2, t = lane & 3;
    const int mt = warp & 3, ntb = (warp >> 2) * 4;
    float acc[4][4] = {};

    for (int k0 = 0; k0 < Klen; k0 += 16) {
        __syncthreads();
        for (int k = tid; k < 1024; k += 256) {
            int r = k >> 4, c = k & 15;
            float xv = X[(size_t)(m0 + r) * ldx + k0 + c];
            float hx = __uint_as_float(f2tf32(xv));
            xh[r][c] = hx;
            xl[r][c] = __uint_as_float(f2tf32(xv - hx));
            float wv = W[(size_t)(o0 + r) * ldw + k0 + c];
            float hw = __uint_as_float(f2tf32(wv));
            wh[r][c] = hw;
            wl[r][c] = __uint_as_float(f2tf32(wv - hw));
        }
        __syncthreads();
#pragma unroll
        for (int kk = 0; kk < 16; kk += 8) {
            unsigned ah0 = __float_as_uint(xh[mt * 16 + g][kk + t]);
            unsigned ah1 = __float_as_uint(xh[mt * 16 + g + 8][kk + t]);
            unsigned ah2 = __float_as_uint(xh[mt * 16 + g][kk + t + 4]);
            unsigned ah3 = __float_as_uint(xh[mt * 16 + g + 8][kk + t + 4]);
            unsigned al0 = __float_as_uint(xl[mt * 16 + g][kk + t]);
            unsigned al1 = __float_as_uint(xl[mt * 16 + g + 8][kk + t]);
            unsigned al2 = __float_as_uint(xl[mt * 16 + g][kk + t + 4]);
            unsigned al3 = __float_as_uint(xl[mt * 16 + g + 8][kk + t + 4]);
#pragma unroll
            for (int ni = 0; ni < 4; ni++) {
                const int wr = (ntb + ni) * 8 + g;
                unsigned bh0 = __float_as_uint(wh[wr][kk + t]);
                unsigned bh1 = __float_as_uint(wh[wr][kk + t + 4]);
                unsigned bl0 = __float_as_uint(wl[wr][kk + t]);
                unsigned bl1 = __float_as_uint(wl[wr][kk + t + 4]);
                MMA_TF32(acc[ni], ah0, ah1, ah2, ah3, bh0, bh1);
                MMA_TF32(acc[ni], ah0, ah1, ah2, ah3, bl0, bl1);
                MMA_TF32(acc[ni], al0, al1, al2, al3, bh0, bh1);
            }
        }
    }
#pragma unroll
    for (int ni = 0; ni < 4; ni++) {
        const int n = o0 + (ntb + ni) * 8 + 2 * t;
        const float b0v = bias ? bias[n] : 0.f;
        const float b1v = bias ? bias[n + 1] : 0.f;
        const int m = m0 + mt * 16 + g;
        Cp[(size_t)m * ldc + n]           = acc[ni][0] + b0v;
        Cp[(size_t)m * ldc + n + 1]       = acc[ni][1] + b1v;
        Cp[(size_t)(m + 8) * ldc + n]     = acc[ni][2] + b0v;
        Cp[(size_t)(m + 8) * ldc + n + 1] = acc[ni][3] + b1v;
    }
}

// ---------------- K2: rotations / frames / norms / packed q ----------------
__global__ void rot_kernel(const float* __restrict__ rot, const float* __restrict__ trans,
                           const float* __restrict__ tpw, const float* __restrict__ b_a2) {
    const int n = blockIdx.x;
    const int tid = threadIdx.x;  // 192
    __shared__ float R[9], t3[3], qn_s[Hh], kn_s[Hh], pwb_s[Hh];
    const float* pr = d_proj + (size_t)n * PROJ_DIM;
    if (tid < 9)  R[tid] = rot[n * 9 + tid];
    if (tid < 3)  t3[tid] = trans[n * 3 + tid];
    if (tid < Hh) {
        qn_s[tid] = 0.f; kn_s[tid] = 0.f;
        float x = tpw[tid];
        float sp = (x > 20.f) ? x : log1pf(__expf(x));
        pwb_s[tid] = -0.5f * sp * POINT_W;
    }
    __syncthreads();

    { int h = tid >> 4, f = tid & 15;
      d_qcat[n * 384 + h * 32 + f] = SCALAR_W * pr[tid]; }
    for (int o = tid; o < 384; o += 192) {
        int h = o >> 5, d = o & 31;
        float v = pr[192 + o];
        if (d < 16) d_kT[(size_t)(h * 29 + d) * Nn + n] = v;
        else        d_vcat[(size_t)n * 480 + h * 16 + (d - 16)] = v;
    }
    if (tid < 48) {
        int m = tid;
        float p0 = pr[576 + 0 * 48 + m];
        float p1 = pr[576 + 1 * 48 + m];
        float p2 = pr[576 + 2 * 48 + m];
        float g0 = R[0] * p0 + R[1] * p1 + R[2] * p2 + t3[0];
        float g1 = R[3] * p0 + R[4] * p1 + R[5] * p2 + t3[1];
        float g2 = R[6] * p0 + R[7] * p1 + R[8] * p2 + t3[2];
        int h = m >> 2, p = m & 3;
        float s = -2.f * pwb_s[h];
        int base = n * 384 + h * 32 + 16 + p * 3;
        d_qcat[base + 0] = s * g0; d_qcat[base + 1] = s * g1; d_qcat[base + 2] = s * g2;
        atomicAdd(&qn_s[h], g0 * g0 + g1 * g1 + g2 * g2);
    } else {
        int m = tid - 48;
        float p0 = pr[720 + 0 * 144 + m];
        float p1 = pr[720 + 1 * 144 + m];
        float p2 = pr[720 + 2 * 144 + m];
        float g0 = R[0] * p0 + R[1] * p1 + R[2] * p2 + t3[0];
        float g1 = R[3] * p0 + R[4] * p1 + R[5] * p2 + t3[1];
        float g2 = R[6] * p0 + R[7] * p1 + R[8] * p2 + t3[2];
        int h = m / 12, pp = m % 12;
        if (pp < 4) {
            int fb = h * 29 + 16 + pp * 3;
            d_kT[(size_t)(fb + 0) * Nn + n] = g0;
            d_kT[(size_t)(fb + 1) * Nn + n] = g1;
            d_kT[(size_t)(fb + 2) * Nn + n] = g2;
            atomicAdd(&kn_s[h], g0 * g0 + g1 * g1 + g2 * g2);
        } else {
            int base = n * 480 + 192 + h * 24 + (pp - 4) * 3;
            d_vcat[base + 0] = g0; d_vcat[base + 1] = g1; d_vcat[base + 2] = g2;
        }
    }
    __syncthreads();
    if (tid < Hh) {
        int qb = n * 384 + tid * 32;
        d_qcat[qb + 28] = pwb_s[tid];
        d_qcat[qb + 29] = pwb_s[tid] * qn_s[tid] + W2D * b_a2[tid];
        d_qcat[qb + 30] = 0.f;
        d_qcat[qb + 31] = 0.f;
        d_kT[(size_t)(tid * 29 + 28) * Nn + n] = kn_s[tid];
    }
}

// ---------------- K3a: scalar/point logits, K=29 GEMM, 8x8 register tile ----------------
__global__ __launch_bounds__(128) void lgsp_kernel(const float* __restrict__ mask) {
    __shared__ float q_s[64][36];
    __shared__ float kt_s[29][132];
    __shared__ float mj_s[128];
    const int jt = blockIdx.x * 128;
    const int it = blockIdx.y * 64;
    const int h  = blockIdx.z;
    const int tid = threadIdx.x;

    for (int k = tid; k < 512; k += 128) {
        int r = k >> 3, c4 = k & 7;
        *(((float4*)&q_s[r][0]) + c4) =
            *(((const float4*)(d_qcat + (size_t)(it + r) * 384 + h * 32)) + c4);
    }
    for (int k = tid; k < 928; k += 128) {
        int f = k >> 5, c4 = k & 31;
        *(((float4*)&kt_s[f][0]) + c4) =
            *(((const float4*)(d_kT + (size_t)(h * 29 + f) * Nn + jt)) + c4);
    }
    if (tid < 128) mj_s[tid] = mask[jt + tid];
    __syncthreads();

    const int tj = tid & 15, ti = tid >> 4;
    float acc[8][8] = {};
#pragma unroll
    for (int f = 0; f < 29; f++) {
        float a[8];
        float4 b0 = *((const float4*)&kt_s[f][tj * 8]);
        float4 b1 = *((const float4*)&kt_s[f][tj * 8 + 4]);
        float b[8] = {b0.x, b0.y, b0.z, b0.w, b1.x, b1.y, b1.z, b1.w};
#pragma unroll
        for (int r = 0; r < 8; r++) a[r] = q_s[ti * 8 + r][f];
#pragma unroll
        for (int r = 0; r < 8; r++)
#pragma unroll
            for (int c = 0; c < 8; c++) acc[r][c] += a[r] * b[c];
    }
#pragma unroll
    for (int r = 0; r < 8; r++) {
        const int ii = it + ti * 8 + r;
        const float mi = mask[ii];
        const float cih = q_s[ti * 8 + r][29];
        float4* orow = (float4*)(d_lgsp + ((size_t)ii * Hh + h) * Nn + jt + tj * 8);
        float4 o0, o1;
        o0.x = acc[r][0] + cih - 100000.f * (1.f - mi * mj_s[tj * 8 + 0]);
        o0.y = acc[r][1] + cih - 100000.f * (1.f - mi * mj_s[tj * 8 + 1]);
        o0.z = acc[r][2] + cih - 100000.f * (1.f - mi * mj_s[tj * 8 + 2]);
        o0.w = acc[r][3] + cih - 100000.f * (1.f - mi * mj_s[tj * 8 + 3]);
        o1.x = acc[r][4] + cih - 100000.f * (1.f - mi * mj_s[tj * 8 + 4]);
        o1.y = acc[r][5] + cih - 100000.f * (1.f - mi * mj_s[tj * 8 + 5]);
        o1.z = acc[r][6] + cih - 100000.f * (1.f - mi * mj_s[tj * 8 + 6]);
        o1.w = acc[r][7] + cih - 100000.f * (1.f - mi * mj_s[tj * 8 + 7]);
        orow[0] = o0; orow[1] = o1;
    }
}

// ---------------- K3b: fused tf32-mma a2d + lgsp + softmax + fp32 r2d ----------------
// 768 blocks, 256 threads, dyn smem 79488 B
__global__ __launch_bounds__(256) void attn_fused_kernel(const float* __restrict__ in2d,
                                                         const float* __restrict__ w_a2) {
    extern __shared__ float sm[];
    float* xs     = sm;                 // 64*132 = 8448
    float* ws     = sm + 8448;          // 16*132 = 2112
    float* attbuf = sm + 10560;         // 768*12 = 9216
    float* red    = sm + 19776;         // 96

    const int i = blockIdx.x;
    const int tid = threadIdx.x;
    const int warp = tid >> 5, lane = tid & 31;
    const int g = lane >> 2, t = lane & 3;
    const int mt = warp & 3, nt = warp >> 2;

    // W -> smem (tf32-rounded); pad rows 12..15 with zeros
    for (int k = tid; k < 1536; k += 256) {
        int h = k >> 7, c = k & 127;
        ws[h * 132 + c] = __uint_as_float(f2tf32(w_a2[k]));
    }
    for (int k = tid; k < 528; k += 256) ws[1584 + k] = 0.f;

    const float4* in4 = (const float4*)in2d + (size_t)i * Nn * 32;

    // ---- phase A: a2d logits via tf32 mma, 12 chunks of 64 j ----
    for (int ch = 0; ch < 12; ch++) {
        __syncthreads();
        const float4* src = in4 + (size_t)ch * 64 * 32;
        for (int k = tid; k < 2048; k += 256) {
            int jl = k >> 5, c4 = k & 31;
            float4 v = src[jl * 32 + c4];
            float4 o;
            o.x = __uint_as_float(f2tf32(v.x));
            o.y = __uint_as_float(f2tf32(v.y));
            o.z = __uint_as_float(f2tf32(v.z));
            o.w = __uint_as_float(f2tf32(v.w));
            *(float4*)&xs[jl * 132 + c4 * 4] = o;
        }
        __syncthreads();
        float acc[4] = {0.f, 0.f, 0.f, 0.f};
        const float* xr0 = &xs[(mt * 16 + g) * 132];
        const float* xr1 = xr0 + 8 * 132;
        const float* wr  = &ws[(nt * 8 + g) * 132];
#pragma unroll
        for (int k0 = 0; k0 < 128; k0 += 8) {
            unsigned a0 = __float_as_uint(xr0[k0 + t]);
            unsigned a1 = __float_as_uint(xr1[k0 + t]);
            unsigned a2 = __float_as_uint(xr0[k0 + t + 4]);
            unsigned a3 = __float_as_uint(xr1[k0 + t + 4]);
            unsigned b0 = __float_as_uint(wr[k0 + t]);
            unsigned b1 = __float_as_uint(wr[k0 + t + 4]);
            MMA_TF32(acc, a0, a1, a2, a3, b0, b1);
        }
        const int h0 = nt * 8 + 2 * t;
        const int j0 = ch * 64 + mt * 16 + g;
        if (h0 < 12) {
            attbuf[j0 * 12 + h0]           = acc[0];
            attbuf[j0 * 12 + h0 + 1]       = acc[1];
            attbuf[(j0 + 8) * 12 + h0]     = acc[2];
            attbuf[(j0 + 8) * 12 + h0 + 1] = acc[3];
        }
    }
    __syncthreads();

    // ---- phase B: + lgsp, softmax ----
    const float* lgp = d_lgsp + (size_t)i * Hh * Nn;
    float acc[12][3];
#pragma unroll
    for (int h = 0; h < 12; h++) {
        float mx = -1e30f;
#pragma unroll
        for (int u = 0; u < 3; u++) {
            int j = tid + 256 * u;
            float L = attbuf[j * 12 + h] * W2D + lgp[h * Nn + j];
            acc[h][u] = L;
            mx = fmaxf(mx, L);
        }
#pragma unroll
        for (int off = 16; off > 0; off >>= 1)
            mx = fmaxf(mx, __shfl_xor_sync(0xffffffffu, mx, off));
        if (lane == 0) red[warp * 12 + h] = mx;
    }
    __syncthreads();
    float mxh[12];
#pragma unroll
    for (int h = 0; h < 12; h++) {
        float m = red[h];
#pragma unroll
        for (int w = 1; w < 8; w++) m = fmaxf(m, red[w * 12 + h]);
        mxh[h] = m;
    }
    __syncthreads();

#pragma unroll
    for (int h = 0; h < 12; h++) {
        float s = 0.f;
#pragma unroll
        for (int u = 0; u < 3; u++) {
            float e = __expf(acc[h][u] - mxh[h]);
            acc[h][u] = e;
            s += e;
        }
#pragma unroll
        for (int off = 16; off > 0; off >>= 1)
            s += __shfl_xor_sync(0xffffffffu, s, off);
        if (lane == 0) red[warp * 12 + h] = s;
    }
    __syncthreads();
    float smh[12];
#pragma unroll
    for (int h = 0; h < 12; h++) {
        float s = 0.f;
#pragma unroll
        for (int w = 0; w < 8; w++) s += red[w * 12 + h];
        smh[h] = 1.f / s;
    }
    __syncthreads();

#pragma unroll
    for (int h = 0; h < 12; h++) {
        float* arow = d_attn + ((size_t)i * Hh + h) * Nn;
#pragma unroll
        for (int u = 0; u < 3; u++) {
            float a = acc[h][u] * smh[h];
            int j = tid + 256 * u;
            arow[j] = a;
            attbuf[j * 12 + h] = a;
        }
    }
    __syncthreads();

    // ---- phase C: r2d = attn[12,768] @ X[768,128], fp32 ----
    {
        const int c4 = tid & 31;
        const int hh = (tid >> 5) & 1;   // heads hh*6..hh*6+5
        const int js = tid >> 6;         // 4 slices of 192 j
        float r2[24] = {};
        const float4* x4p = in4 + c4;
        const float* abase = attbuf + hh * 6;
        const int jbeg = js * 192;
#pragma unroll 2
        for (int j = jbeg; j < jbeg + 192; j++) {
            float4 x = x4p[(size_t)j * 32];
            const float* ab = abase + j * 12;
            float a0 = ab[0], a1 = ab[1], a2 = ab[2], a3 = ab[3], a4 = ab[4], a5 = ab[5];
            r2[0]  += a0 * x.x; r2[1]  += a0 * x.y; r2[2]  += a0 * x.z; r2[3]  += a0 * x.w;
            r2[4]  += a1 * x.x; r2[5]  += a1 * x.y; r2[6]  += a1 * x.z; r2[7]  += a1 * x.w;
            r2[8]  += a2 * x.x; r2[9]  += a2 * x.y; r2[10] += a2 * x.z; r2[11] += a2 * x.w;
            r2[12] += a3 * x.x; r2[13] += a3 * x.y; r2[14] += a3 * x.z; r2[15] += a3 * x.w;
            r2[16] += a4 * x.x; r2[17] += a4 * x.y; r2[18] += a4 * x.z; r2[19] += a4 * x.w;
            r2[20] += a5 * x.x; r2[21] += a5 * x.y; r2[22] += a5 * x.z; r2[23] += a5 * x.w;
        }
        __syncthreads();   // xs/ws regions free for reduction (attbuf untouched)
        float* redc = sm;  // needs 4*1536 = 6144 floats < 10560
#pragma unroll
        for (int e = 0; e < 6; e++)
#pragma unroll
            for (int u = 0; u < 4; u++)
                redc[js * 1536 + (hh * 6 + e) * 128 + c4 * 4 + u] = r2[e * 4 + u];
        __syncthreads();
        float* fa = d_fa + (size_t)i * FA_DIM + 576;
        for (int k = tid; k < 1536; k += 256)
            fa[k] = redc[k] + redc[1536 + k] + redc[3072 + k] + redc[4608 + k];
    }
}

// ---------------- K6: PV tiled GEMM ----------------
__global__ void pv_kernel() {
    __shared__ float att_s[64 * 33];
    __shared__ float v_s[32 * 40];
    const int i0 = blockIdx.x * 64;
    const int h = blockIdx.y;
    const int tid = threadIdx.x;
    const int io2 = tid & 31, ov = tid >> 5;
    float acc0[5] = {}, acc1[5] = {};

    for (int jt = 0; jt < Nn; jt += 32) {
        __syncthreads();
#pragma unroll
        for (int k = 0; k < 8; k++) {
            int f = tid + 256 * k;
            int il = f >> 5, jl = f & 31;
            att_s[il * 33 + jl] = d_attn[((size_t)(i0 + il) * 12 + h) * Nn + jt + jl];
        }
#pragma unroll
        for (int k = 0; k < 5; k++) {
            int f = tid + 256 * k;
            int jl = f / 40, o = f % 40;
            const float* vr = d_vcat + (size_t)(jt + jl) * 480;
            v_s[jl * 40 + o] = (o < 16) ? vr[h * 16 + o] : vr[192 + h * 24 + (o - 16)];
        }
        __syncthreads();
#pragma unroll 4
        for (int jl = 0; jl < 32; jl++) {
            float a0 = att_s[io2 * 33 + jl];
            float a1 = att_s[(io2 + 32) * 33 + jl];
#pragma unroll
            for (int u = 0; u < 5; u++) {
                float vv = v_s[jl * 40 + ov * 5 + u];
                acc0[u] += a0 * vv;
                acc1[u] += a1 * vv;
            }
        }
    }
#pragma unroll
    for (int u = 0; u < 5; u++) {
        int o = ov * 5 + u;
        int i_a = i0 + io2, i_b = i0 + io2 + 32;
        if (o < 16) {
            d_fa[(size_t)i_a * FA_DIM + h * 16 + o] = acc0[u];
            d_fa[(size_t)i_b * FA_DIM + h * 16 + o] = acc1[u];
        } else {
            d_rpg[i_a * 288 + h * 24 + (o - 16)] = acc0[u];
            d_rpg[i_b * 288 + h * 24 + (o - 16)] = acc1[u];
        }
    }
}

// ---------------- K7: local frame + dist ----------------
__global__ void local_kernel(const float* __restrict__ rot, const float* __restrict__ trans) {
    __shared__ float rpg_s[288], loc[288], Ri[9], ti[3];
    const int i = blockIdx.x;
    const int tid = threadIdx.x;  // 288
    rpg_s[tid] = d_rpg[i * 288 + tid];
    if (tid < 9) Ri[tid] = rot[i * 9 + tid];
    if (tid < 3) ti[tid] = trans[i * 3 + tid];
    __syncthreads();
    float* fa = d_fa + (size_t)i * FA_DIM;
    const int idim = tid / 96, m = tid % 96;
    const int hh = m >> 3, p = m & 7;
    const int base = hh * 24 + p * 3;
    float v0 = rpg_s[base + 0] - ti[0];
    float v1 = rpg_s[base + 1] - ti[1];
    float v2 = rpg_s[base + 2] - ti[2];
    float l = Ri[idim] * v0 + Ri[3 + idim] * v1 + Ri[6 + idim] * v2;
    loc[idim * 96 + m] = l;
    fa[192 + idim * 96 + m] = l;
    __syncthreads();
    if (tid < 96) {
        float l0 = loc[tid], l1 = loc[96 + tid], l2 = loc[192 + tid];
        fa[480 + tid] = sqrtf(1e-8f + l0 * l0 + l1 * l1 + l2 * l2);
    }
}

// ---------------- K8: reduce out partials + bias ----------------
__global__ void reduce_out_kernel(const float* __restrict__ b_out, float* __restrict__ out) {
    const int idx = blockIdx.x * 256 + threadIdx.x;
    const int total = Nn * 384;
    if (idx < total) {
        out[idx] = b_out[idx % 384] + d_part[idx] + d_part[total + idx]
                 + d_part[2 * total + idx] + d_part[3 * total + idx];
    }
}

// ---------------- launch ----------------
extern "C" void kernel_launch(void* const* d_in, const int* in_sizes, int n_in,
                              void* d_out, int out_size) {
    const float* inputs_1d = (const float*)d_in[0];
    const float* inputs_2d = (const float*)d_in[1];
    const float* mask      = (const float*)d_in[2];
    const float* rotation  = (const float*)d_in[3];
    const float* translat  = (const float*)d_in[4];
    const float* w_qs      = (const float*)d_in[5];
    const float* b_qs      = (const float*)d_in[6];
    const float* w_kvs     = (const float*)d_in[7];
    const float* b_kvs     = (const float*)d_in[8];
    const float* w_qp      = (const float*)d_in[9];
    const float* b_qp      = (const float*)d_in[10];
    const float* w_kvp     = (const float*)d_in[11];
    const float* b_kvp     = (const float*)d_in[12];
    const float* tpw       = (const float*)d_in[13];
    const float* w_a2      = (const float*)d_in[14];
    const float* b_a2      = (const float*)d_in[15];
    const float* w_out     = (const float*)d_in[16];
    const float* b_out     = (const float*)d_in[17];
    float* out = (float*)d_out;

    void *p_wcat, *p_bcat, *p_proj, *p_fa, *p_part;
    cudaGetSymbolAddress(&p_wcat, d_wcat);
    cudaGetSymbolAddress(&p_bcat, d_bcat);
    cudaGetSymbolAddress(&p_proj, d_proj);
    cudaGetSymbolAddress(&p_fa,   d_fa);
    cudaGetSymbolAddress(&p_part, d_part);

    concat_w_kernel<<<256, 256>>>(w_qs, w_kvs, w_qp, w_kvp, b_qs, b_kvs, b_qp, b_kvp);

    // projections: [768 x 384] @ [1152 x 384]^T  (split-tf32)
    gemm_tf3_kernel<<<dim3(PROJ_DIM / 64, Nn / 64, 1), 256>>>(
        inputs_1d, C1d, 0, (const float*)p_wcat, C1d, 0,
        (const float*)p_bcat, (float*)p_proj, PROJ_DIM, 0, C1d);

    rot_kernel<<<Nn, 192>>>(rotation, translat, tpw, b_a2);

    lgsp_kernel<<<dim3(6, 12, 12), 128>>>(mask);

    {
        const int smem = 19872 * (int)sizeof(float);
        cudaFuncSetAttribute(attn_fused_kernel, cudaFuncAttributeMaxDynamicSharedMemorySize, smem);
        attn_fused_kernel<<<Nn, 256, smem>>>(inputs_2d, w_a2);
    }

    pv_kernel<<<dim3(Nn / 64, Hh), 256>>>();
    local_kernel<<<Nn, 288>>>(rotation, translat);

    // out GEMM: K split 4 x 528 on z (split-tf32), then reduce
    gemm_tf3_kernel<<<dim3(384 / 64, Nn / 64, 4), 256>>>(
        (const float*)p_fa, FA_DIM, 528, w_out, FA_DIM, 528,
        nullptr, (float*)p_part, 384, (long long)Nn * 384, 528);
    reduce_out_kernel<<<(Nn * 384 + 255) / 256, 256>>>(b_out, out);
}

// round 7
// speedup vs baseline: 1.0079x; 1.0079x over previous
#include <cuda_runtime.h>
#include <math.h>
#include <stdint.h>

#define Hh   12
#define Nn   768
#define C1d  384
#define C2d  128
#define PROJ_DIM 1152
#define FA_DIM   2112

#define SCALAR_W 0.14433756729740643f
#define POINT_W  0.13608276348795434f
#define W2D      0.5773502691896258f

// ---------------- scratch ----------------
__device__ float d_proj[Nn * PROJ_DIM];
__device__ float d_qcat[Nn * 384];
__device__ float d_kT[Hh * 29 * Nn];
__device__ float d_vcat[Nn * 480];
__device__ float d_lgsp[Nn * Hh * Nn];
__device__ float d_attn[Hh * Nn * Nn];
__device__ float d_rpg[Nn * 288];
__device__ float d_fa[Nn * FA_DIM];
__device__ float d_part[4 * Nn * 384];

// ---------------- tf32 helpers ----------------
__device__ __forceinline__ unsigned f2tf32(float x) {
    unsigned r;
    asm("cvt.rna.tf32.f32 %0, %1;" : "=r"(r) : "f"(x));
    return r;
}

#define MMA_TF32(ac, A0, A1, A2, A3, B0, B1)                                   \
    asm volatile(                                                              \
        "mma.sync.aligned.m16n8k8.row.col.f32.tf32.tf32.f32 "                  \
        "{%0,%1,%2,%3},{%4,%5,%6,%7},{%8,%9},{%0,%1,%2,%3};"                   \
        : "+f"(ac[0]), "+f"(ac[1]), "+f"(ac[2]), "+f"(ac[3])                   \
        : "r"(A0), "r"(A1), "r"(A2), "r"(A3), "r"(B0), "r"(B1))

// ---------------- K1: projection GEMM (split-tf32) with inline weight concat ----------------
// C[768, 1152] = X[768,384] @ Wcat[1152,384]^T + bcat
__global__ __launch_bounds__(256) void gemm_proj_kernel(
        const float* __restrict__ X,
        const float* __restrict__ wqs, const float* __restrict__ wkvs,
        const float* __restrict__ wqp, const float* __restrict__ wkvp,
        const float* __restrict__ bqs, const float* __restrict__ bkvs,
        const float* __restrict__ bqp, const float* __restrict__ bkvp) {
    __shared__ float xh[64][20], xl[64][20], wh[64][20], wl[64][20];
    const int m0 = blockIdx.y * 64, o0 = blockIdx.x * 64;
    const int tid = threadIdx.x;
    const int warp = tid >> 5, lane = tid & 31, g = lane >> 2, t = lane & 3;
    const int mt = warp & 3, ntb = (warp >> 2) * 4;
    float acc[4][4] = {};

    for (int k0 = 0; k0 < C1d; k0 += 16) {
        __syncthreads();
        for (int k = tid; k < 1024; k += 256) {
            int r = k >> 4, c = k & 15;
            float xv = X[(size_t)(m0 + r) * C1d + k0 + c];
            float hx = __uint_as_float(f2tf32(xv));
            xh[r][c] = hx;
            xl[r][c] = __uint_as_float(f2tf32(xv - hx));
            int o = o0 + r;
            const float* wrow;
            if (o < 192)      wrow = wqs  + (size_t)o * C1d;
            else if (o < 576) wrow = wkvs + (size_t)(o - 192) * C1d;
            else if (o < 720) wrow = wqp  + (size_t)(o - 576) * C1d;
            else              wrow = wkvp + (size_t)(o - 720) * C1d;
            float wv = wrow[k0 + c];
            float hw = __uint_as_float(f2tf32(wv));
            wh[r][c] = hw;
            wl[r][c] = __uint_as_float(f2tf32(wv - hw));
        }
        __syncthreads();
#pragma unroll
        for (int kk = 0; kk < 16; kk += 8) {
            unsigned ah0 = __float_as_uint(xh[mt * 16 + g][kk + t]);
            unsigned ah1 = __float_as_uint(xh[mt * 16 + g + 8][kk + t]);
            unsigned ah2 = __float_as_uint(xh[mt * 16 + g][kk + t + 4]);
            unsigned ah3 = __float_as_uint(xh[mt * 16 + g + 8][kk + t + 4]);
            unsigned al0 = __float_as_uint(xl[mt * 16 + g][kk + t]);
            unsigned al1 = __float_as_uint(xl[mt * 16 + g + 8][kk + t]);
            unsigned al2 = __float_as_uint(xl[mt * 16 + g][kk + t + 4]);
            unsigned al3 = __float_as_uint(xl[mt * 16 + g + 8][kk + t + 4]);
#pragma unroll
            for (int ni = 0; ni < 4; ni++) {
                const int wr = (ntb + ni) * 8 + g;
                unsigned bh0 = __float_as_uint(wh[wr][kk + t]);
                unsigned bh1 = __float_as_uint(wh[wr][kk + t + 4]);
                unsigned bl0 = __float_as_uint(wl[wr][kk + t]);
                unsigned bl1 = __float_as_uint(wl[wr][kk + t + 4]);
                MMA_TF32(acc[ni], ah0, ah1, ah2, ah3, bh0, bh1);
                MMA_TF32(acc[ni], ah0, ah1, ah2, ah3, bl0, bl1);
                MMA_TF32(acc[ni], al0, al1, al2, al3, bh0, bh1);
            }
        }
    }
#pragma unroll
    for (int ni = 0; ni < 4; ni++) {
        const int n = o0 + (ntb + ni) * 8 + 2 * t;
#pragma unroll
        for (int q = 0; q < 2; q++) {
            int o = n + q;
            float bv;
            if (o < 192)      bv = bqs[o];
            else if (o < 576) bv = bkvs[o - 192];
            else if (o < 720) bv = bqp[o - 576];
            else              bv = bkvp[o - 720];
            const int m = m0 + mt * 16 + g;
            d_proj[(size_t)m * PROJ_DIM + o]       = acc[ni][0 + q] + bv;
            d_proj[(size_t)(m + 8) * PROJ_DIM + o] = acc[ni][2 + q] + bv;
        }
    }
}

// ---------------- out-GEMM (split-tf32), K-split on z ----------------
__global__ __launch_bounds__(256) void gemm_out_kernel(const float* __restrict__ Wo) {
    __shared__ float xh[64][20], xl[64][20], wh[64][20], wl[64][20];
    const int z = blockIdx.z;
    const float* X = d_fa + z * 528;
    const float* W = Wo + z * 528;
    float* Cp = d_part + (size_t)z * (Nn * 384);
    const int m0 = blockIdx.y * 64, o0 = blockIdx.x * 64;
    const int tid = threadIdx.x;
    const int warp = tid >> 5, lane = tid & 31, g = lane >> 2, t = lane & 3;
    const int mt = warp & 3, ntb = (warp >> 2) * 4;
    float acc[4][4] = {};

    for (int k0 = 0; k0 < 528; k0 += 16) {
        __syncthreads();
        for (int k = tid; k < 1024; k += 256) {
            int r = k >> 4, c = k & 15;
            float xv = X[(size_t)(m0 + r) * FA_DIM + k0 + c];
            float hx = __uint_as_float(f2tf32(xv));
            xh[r][c] = hx;
            xl[r][c] = __uint_as_float(f2tf32(xv - hx));
            float wv = W[(size_t)(o0 + r) * FA_DIM + k0 + c];
            float hw = __uint_as_float(f2tf32(wv));
            wh[r][c] = hw;
            wl[r][c] = __uint_as_float(f2tf32(wv - hw));
        }
        __syncthreads();
#pragma unroll
        for (int kk = 0; kk < 16; kk += 8) {
            unsigned ah0 = __float_as_uint(xh[mt * 16 + g][kk + t]);
            unsigned ah1 = __float_as_uint(xh[mt * 16 + g + 8][kk + t]);
            unsigned ah2 = __float_as_uint(xh[mt * 16 + g][kk + t + 4]);
            unsigned ah3 = __float_as_uint(xh[mt * 16 + g + 8][kk + t + 4]);
            unsigned al0 = __float_as_uint(xl[mt * 16 + g][kk + t]);
            unsigned al1 = __float_as_uint(xl[mt * 16 + g + 8][kk + t]);
            unsigned al2 = __float_as_uint(xl[mt * 16 + g][kk + t + 4]);
            unsigned al3 = __float_as_uint(xl[mt * 16 + g + 8][kk + t + 4]);
#pragma unroll
            for (int ni = 0; ni < 4; ni++) {
                const int wr = (ntb + ni) * 8 + g;
                unsigned bh0 = __float_as_uint(wh[wr][kk + t]);
                unsigned bh1 = __float_as_uint(wh[wr][kk + t + 4]);
                unsigned bl0 = __float_as_uint(wl[wr][kk + t]);
                unsigned bl1 = __float_as_uint(wl[wr][kk + t + 4]);
                MMA_TF32(acc[ni], ah0, ah1, ah2, ah3, bh0, bh1);
                MMA_TF32(acc[ni], ah0, ah1, ah2, ah3, bl0, bl1);
                MMA_TF32(acc[ni], al0, al1, al2, al3, bh0, bh1);
            }
        }
    }
#pragma unroll
    for (int ni = 0; ni < 4; ni++) {
        const int n = o0 + (ntb + ni) * 8 + 2 * t;
        const int m = m0 + mt * 16 + g;
        Cp[(size_t)m * 384 + n]           = acc[ni][0];
        Cp[(size_t)m * 384 + n + 1]       = acc[ni][1];
        Cp[(size_t)(m + 8) * 384 + n]     = acc[ni][2];
        Cp[(size_t)(m + 8) * 384 + n + 1] = acc[ni][3];
    }
}

// ---------------- K2: rotations / frames / norms / packed q ----------------
__global__ void rot_kernel(const float* __restrict__ rot, const float* __restrict__ trans,
                           const float* __restrict__ tpw, const float* __restrict__ b_a2) {
    const int n = blockIdx.x;
    const int tid = threadIdx.x;  // 192
    __shared__ float R[9], t3[3], qn_s[Hh], kn_s[Hh], pwb_s[Hh];
    const float* pr = d_proj + (size_t)n * PROJ_DIM;
    if (tid < 9)  R[tid] = rot[n * 9 + tid];
    if (tid < 3)  t3[tid] = trans[n * 3 + tid];
    if (tid < Hh) {
        qn_s[tid] = 0.f; kn_s[tid] = 0.f;
        float x = tpw[tid];
        float sp = (x > 20.f) ? x : log1pf(__expf(x));
        pwb_s[tid] = -0.5f * sp * POINT_W;
    }
    __syncthreads();

    { int h = tid >> 4, f = tid & 15;
      d_qcat[n * 384 + h * 32 + f] = SCALAR_W * pr[tid]; }
    for (int o = tid; o < 384; o += 192) {
        int h = o >> 5, d = o & 31;
        float v = pr[192 + o];
        if (d < 16) d_kT[(size_t)(h * 29 + d) * Nn + n] = v;
        else        d_vcat[(size_t)n * 480 + h * 16 + (d - 16)] = v;
    }
    if (tid < 48) {
        int m = tid;
        float p0 = pr[576 + 0 * 48 + m];
        float p1 = pr[576 + 1 * 48 + m];
        float p2 = pr[576 + 2 * 48 + m];
        float g0 = R[0] * p0 + R[1] * p1 + R[2] * p2 + t3[0];
        float g1 = R[3] * p0 + R[4] * p1 + R[5] * p2 + t3[1];
        float g2 = R[6] * p0 + R[7] * p1 + R[8] * p2 + t3[2];
        int h = m >> 2, p = m & 3;
        float s = -2.f * pwb_s[h];
        int base = n * 384 + h * 32 + 16 + p * 3;
        d_qcat[base + 0] = s * g0; d_qcat[base + 1] = s * g1; d_qcat[base + 2] = s * g2;
        atomicAdd(&qn_s[h], g0 * g0 + g1 * g1 + g2 * g2);
    } else {
        int m = tid - 48;
        float p0 = pr[720 + 0 * 144 + m];
        float p1 = pr[720 + 1 * 144 + m];
        float p2 = pr[720 + 2 * 144 + m];
        float g0 = R[0] * p0 + R[1] * p1 + R[2] * p2 + t3[0];
        float g1 = R[3] * p0 + R[4] * p1 + R[5] * p2 + t3[1];
        float g2 = R[6] * p0 + R[7] * p1 + R[8] * p2 + t3[2];
        int h = m / 12, pp = m % 12;
        if (pp < 4) {
            int fb = h * 29 + 16 + pp * 3;
            d_kT[(size_t)(fb + 0) * Nn + n] = g0;
            d_kT[(size_t)(fb + 1) * Nn + n] = g1;
            d_kT[(size_t)(fb + 2) * Nn + n] = g2;
            atomicAdd(&kn_s[h], g0 * g0 + g1 * g1 + g2 * g2);
        } else {
            int base = n * 480 + 192 + h * 24 + (pp - 4) * 3;
            d_vcat[base + 0] = g0; d_vcat[base + 1] = g1; d_vcat[base + 2] = g2;
        }
    }
    __syncthreads();
    if (tid < Hh) {
        int qb = n * 384 + tid * 32;
        d_qcat[qb + 28] = pwb_s[tid];
        d_qcat[qb + 29] = pwb_s[tid] * qn_s[tid] + W2D * b_a2[tid];
        d_qcat[qb + 30] = 0.f;
        d_qcat[qb + 31] = 0.f;
        d_kT[(size_t)(tid * 29 + 28) * Nn + n] = kn_s[tid];
    }
}

// ---------------- K3a: scalar/point logits, K=29 GEMM, 8x8 register tile ----------------
__global__ __launch_bounds__(128) void lgsp_kernel(const float* __restrict__ mask) {
    __shared__ float q_s[64][36];
    __shared__ float kt_s[29][132];
    __shared__ float mj_s[128];
    const int jt = blockIdx.x * 128;
    const int it = blockIdx.y * 64;
    const int h  = blockIdx.z;
    const int tid = threadIdx.x;

    for (int k = tid; k < 512; k += 128) {
        int r = k >> 3, c4 = k & 7;
        *(((float4*)&q_s[r][0]) + c4) =
            *(((const float4*)(d_qcat + (size_t)(it + r) * 384 + h * 32)) + c4);
    }
    for (int k = tid; k < 928; k += 128) {
        int f = k >> 5, c4 = k & 31;
        *(((float4*)&kt_s[f][0]) + c4) =
            *(((const float4*)(d_kT + (size_t)(h * 29 + f) * Nn + jt)) + c4);
    }
    if (tid < 128) mj_s[tid] = mask[jt + tid];
    __syncthreads();

    const int tj = tid & 15, ti = tid >> 4;
    float acc[8][8] = {};
#pragma unroll
    for (int f = 0; f < 29; f++) {
        float a[8];
        float4 b0 = *((const float4*)&kt_s[f][tj * 8]);
        float4 b1 = *((const float4*)&kt_s[f][tj * 8 + 4]);
        float b[8] = {b0.x, b0.y, b0.z, b0.w, b1.x, b1.y, b1.z, b1.w};
#pragma unroll
        for (int r = 0; r < 8; r++) a[r] = q_s[ti * 8 + r][f];
#pragma unroll
        for (int r = 0; r < 8; r++)
#pragma unroll
            for (int c = 0; c < 8; c++) acc[r][c] += a[r] * b[c];
    }
#pragma unroll
    for (int r = 0; r < 8; r++) {
        const int ii = it + ti * 8 + r;
        const float mi = mask[ii];
        const float cih = q_s[ti * 8 + r][29];
        float4* orow = (float4*)(d_lgsp + ((size_t)ii * Hh + h) * Nn + jt + tj * 8);
        float4 o0, o1;
        o0.x = acc[r][0] + cih - 100000.f * (1.f - mi * mj_s[tj * 8 + 0]);
        o0.y = acc[r][1] + cih - 100000.f * (1.f - mi * mj_s[tj * 8 + 1]);
        o0.z = acc[r][2] + cih - 100000.f * (1.f - mi * mj_s[tj * 8 + 2]);
        o0.w = acc[r][3] + cih - 100000.f * (1.f - mi * mj_s[tj * 8 + 3]);
        o1.x = acc[r][4] + cih - 100000.f * (1.f - mi * mj_s[tj * 8 + 4]);
        o1.y = acc[r][5] + cih - 100000.f * (1.f - mi * mj_s[tj * 8 + 5]);
        o1.z = acc[r][6] + cih - 100000.f * (1.f - mi * mj_s[tj * 8 + 6]);
        o1.w = acc[r][7] + cih - 100000.f * (1.f - mi * mj_s[tj * 8 + 7]);
        orow[0] = o0; orow[1] = o1;
    }
}

// ---------------- K3b: fused a2d GEMM + lgsp + softmax + r2d (fp32) ----------------
// 768 blocks, 256 threads, dyn smem 105024 B
__global__ __launch_bounds__(256) void attn_fused_kernel(const float* __restrict__ in2d,
                                                         const float* __restrict__ w_a2) {
    extern __shared__ float sm[];
    float4* xs4 = (float4*)sm;                 // 15360 floats; reused as red-buf
    float4* ws4 = (float4*)(sm + 15360);       // 1584 floats
    float* att_s = sm + 16944;                 // 9216 floats
    float* red   = sm + 26160;                 // 96 floats

    const int i = blockIdx.x;
    const int tid = threadIdx.x;
    const int wid = tid >> 5, lane = tid & 31;

    const float4* w4g = (const float4*)w_a2;
    for (int k = tid; k < 384; k += 256)
        ws4[(k >> 5) * 33 + (k & 31)] = w4g[k];

    float acc[12][3] = {};
    const float4* in4 = (const float4*)in2d + (size_t)i * Nn * 32;

    // ---- phase A: a2d GEMM ----
    for (int cc = 0; cc < 8; cc++) {
        __syncthreads();
        for (int k = tid; k < 3072; k += 256) {
            int j = k >> 2, c4 = k & 3;
            xs4[j * 5 + c4] = in4[(size_t)j * 32 + cc * 4 + c4];
        }
        __syncthreads();
#pragma unroll
        for (int c4 = 0; c4 < 4; c4++) {
            float4 xv[3];
#pragma unroll
            for (int u = 0; u < 3; u++) xv[u] = xs4[(tid + 256 * u) * 5 + c4];
#pragma unroll
            for (int h = 0; h < 12; h++) {
                float4 wv = ws4[h * 33 + cc * 4 + c4];
#pragma unroll
                for (int u = 0; u < 3; u++)
                    acc[h][u] += xv[u].x * wv.x + xv[u].y * wv.y + xv[u].z * wv.z + xv[u].w * wv.w;
            }
        }
    }

    // ---- phase B: + lgsp, softmax ----
    const float* lgp = d_lgsp + (size_t)i * Hh * Nn;
#pragma unroll
    for (int h = 0; h < 12; h++) {
        float mx = -1e30f;
#pragma unroll
        for (int u = 0; u < 3; u++) {
            float L = acc[h][u] * W2D + lgp[h * Nn + tid + 256 * u];
            acc[h][u] = L;
            mx = fmaxf(mx, L);
        }
#pragma unroll
        for (int off = 16; off > 0; off >>= 1)
            mx = fmaxf(mx, __shfl_xor_sync(0xffffffffu, mx, off));
        if (lane == 0) red[wid * 12 + h] = mx;
    }
    __syncthreads();
    float mxh[12];
#pragma unroll
    for (int h = 0; h < 12; h++) {
        float m = red[h];
#pragma unroll
        for (int w = 1; w < 8; w++) m = fmaxf(m, red[w * 12 + h]);
        mxh[h] = m;
    }
    __syncthreads();

#pragma unroll
    for (int h = 0; h < 12; h++) {
        float s = 0.f;
#pragma unroll
        for (int u = 0; u < 3; u++) {
            float e = __expf(acc[h][u] - mxh[h]);
            acc[h][u] = e;
            s += e;
        }
#pragma unroll
        for (int off = 16; off > 0; off >>= 1)
            s += __shfl_xor_sync(0xffffffffu, s, off);
        if (lane == 0) red[wid * 12 + h] = s;
    }
    __syncthreads();
    float smh[12];
#pragma unroll
    for (int h = 0; h < 12; h++) {
        float s = 0.f;
#pragma unroll
        for (int w = 0; w < 8; w++) s += red[w * 12 + h];
        smh[h] = 1.f / s;
    }

#pragma unroll
    for (int h = 0; h < 12; h++) {
        float* arow = d_attn + ((size_t)i * Hh + h) * Nn;
#pragma unroll
        for (int u = 0; u < 3; u++) {
            float a = acc[h][u] * smh[h];
            int j = tid + 256 * u;
            arow[j] = a;
            att_s[j * 12 + h] = a;
        }
    }
    __syncthreads();

    // ---- phase C: r2d = attn[12,768] @ X[768,128] ----
    {
        const float4* as4 = (const float4*)att_s;
        const int c4 = tid & 31, js = tid >> 5;
        float r2[48] = {};
        const float4* x4p = in4 + c4;
        const int jbeg = js * 96;
        for (int j = jbeg; j < jbeg + 96; j += 2) {
            float4 xa = x4p[(size_t)j * 32];
            float4 xb = x4p[(size_t)(j + 1) * 32];
            float4 a0 = as4[j * 3 + 0], a1 = as4[j * 3 + 1], a2 = as4[j * 3 + 2];
            float4 b0 = as4[j * 3 + 3], b1 = as4[j * 3 + 4], b2 = as4[j * 3 + 5];
            float aa[12] = {a0.x, a0.y, a0.z, a0.w, a1.x, a1.y, a1.z, a1.w, a2.x, a2.y, a2.z, a2.w};
            float bb[12] = {b0.x, b0.y, b0.z, b0.w, b1.x, b1.y, b1.z, b1.w, b2.x, b2.y, b2.z, b2.w};
#pragma unroll
            for (int h = 0; h < 12; h++) {
                r2[h * 4 + 0] += aa[h] * xa.x + bb[h] * xb.x;
                r2[h * 4 + 1] += aa[h] * xa.y + bb[h] * xb.y;
                r2[h * 4 + 2] += aa[h] * xa.z + bb[h] * xb.z;
                r2[h * 4 + 3] += aa[h] * xa.w + bb[h] * xb.w;
            }
        }
        __syncthreads();
        float* redc = sm;
#pragma unroll
        for (int k = 0; k < 48; k++) {
            int h = k >> 2, u = k & 3;
            redc[js * 1536 + h * 128 + c4 * 4 + u] = r2[k];
        }
        __syncthreads();
        float* fa = d_fa + (size_t)i * FA_DIM + 576;
        for (int k = tid; k < 1536; k += 256) {
            float s = 0.f;
#pragma unroll
            for (int z = 0; z < 8; z++) s += redc[z * 1536 + k];
            fa[k] = s;
        }
    }
}

// ---------------- K6: PV tiled GEMM ----------------
__global__ void pv_kernel() {
    __shared__ float att_s[64 * 33];
    __shared__ float v_s[32 * 40];
    const int i0 = blockIdx.x * 64;
    const int h = blockIdx.y;
    const int tid = threadIdx.x;
    const int io2 = tid & 31, ov = tid >> 5;
    float acc0[5] = {}, acc1[5] = {};

    for (int jt = 0; jt < Nn; jt += 32) {
        __syncthreads();
#pragma unroll
        for (int k = 0; k < 8; k++) {
            int f = tid + 256 * k;
            int il = f >> 5, jl = f & 31;
            att_s[il * 33 + jl] = d_attn[((size_t)(i0 + il) * 12 + h) * Nn + jt + jl];
        }
#pragma unroll
        for (int k = 0; k < 5; k++) {
            int f = tid + 256 * k;
            int jl = f / 40, o = f % 40;
            const float* vr = d_vcat + (size_t)(jt + jl) * 480;
            v_s[jl * 40 + o] = (o < 16) ? vr[h * 16 + o] : vr[192 + h * 24 + (o - 16)];
        }
        __syncthreads();
#pragma unroll 4
        for (int jl = 0; jl < 32; jl++) {
            float a0 = att_s[io2 * 33 + jl];
            float a1 = att_s[(io2 + 32) * 33 + jl];
#pragma unroll
            for (int u = 0; u < 5; u++) {
                float vv = v_s[jl * 40 + ov * 5 + u];
                acc0[u] += a0 * vv;
                acc1[u] += a1 * vv;
            }
        }
    }
#pragma unroll
    for (int u = 0; u < 5; u++) {
        int o = ov * 5 + u;
        int i_a = i0 + io2, i_b = i0 + io2 + 32;
        if (o < 16) {
            d_fa[(size_t)i_a * FA_DIM + h * 16 + o] = acc0[u];
            d_fa[(size_t)i_b * FA_DIM + h * 16 + o] = acc1[u];
        } else {
            d_rpg[i_a * 288 + h * 24 + (o - 16)] = acc0[u];
            d_rpg[i_b * 288 + h * 24 + (o - 16)] = acc1[u];
        }
    }
}

// ---------------- K7: local frame + dist ----------------
__global__ void local_kernel(const float* __restrict__ rot, const float* __restrict__ trans) {
    __shared__ float rpg_s[288], loc[288], Ri[9], ti[3];
    const int i = blockIdx.x;
    const int tid = threadIdx.x;  // 288
    rpg_s[tid] = d_rpg[i * 288 + tid];
    if (tid < 9) Ri[tid] = rot[i * 9 + tid];
    if (tid < 3) ti[tid] = trans[i * 3 + tid];
    __syncthreads();
    float* fa = d_fa + (size_t)i * FA_DIM;
    const int idim = tid / 96, m = tid % 96;
    const int hh = m >> 3, p = m & 7;
    const int base = hh * 24 + p * 3;
    float v0 = rpg_s[base + 0] - ti[0];
    float v1 = rpg_s[base + 1] - ti[1];
    float v2 = rpg_s[base + 2] - ti[2];
    float l = Ri[idim] * v0 + Ri[3 + idim] * v1 + Ri[6 + idim] * v2;
    loc[idim * 96 + m] = l;
    fa[192 + idim * 96 + m] = l;
    __syncthreads();
    if (tid < 96) {
        float l0 = loc[tid], l1 = loc[96 + tid], l2 = loc[192 + tid];
        fa[480 + tid] = sqrtf(1e-8f + l0 * l0 + l1 * l1 + l2 * l2);
    }
}

// ---------------- K8: reduce out partials + bias ----------------
__global__ void reduce_out_kernel(const float* __restrict__ b_out, float* __restrict__ out) {
    const int idx = blockIdx.x * 256 + threadIdx.x;
    const int total = Nn * 384;
    if (idx < total) {
        out[idx] = b_out[idx % 384] + d_part[idx] + d_part[total + idx]
                 + d_part[2 * total + idx] + d_part[3 * total + idx];
    }
}

// ---------------- launch ----------------
extern "C" void kernel_launch(void* const* d_in, const int* in_sizes, int n_in,
                              void* d_out, int out_size) {
    const float* inputs_1d = (const float*)d_in[0];
    const float* inputs_2d = (const float*)d_in[1];
    const float* mask      = (const float*)d_in[2];
    const float* rotation  = (const float*)d_in[3];
    const float* translat  = (const float*)d_in[4];
    const float* w_qs      = (const float*)d_in[5];
    const float* b_qs      = (const float*)d_in[6];
    const float* w_kvs     = (const float*)d_in[7];
    const float* b_kvs     = (const float*)d_in[8];
    const float* w_qp      = (const float*)d_in[9];
    const float* b_qp      = (const float*)d_in[10];
    const float* w_kvp     = (const float*)d_in[11];
    const float* b_kvp     = (const float*)d_in[12];
    const float* tpw       = (const float*)d_in[13];
    const float* w_a2      = (const float*)d_in[14];
    const float* b_a2      = (const float*)d_in[15];
    const float* w_out     = (const float*)d_in[16];
    const float* b_out     = (const float*)d_in[17];
    float* out = (float*)d_out;

    // 1) projections (inline weight concat)
    gemm_proj_kernel<<<dim3(PROJ_DIM / 64, Nn / 64), 256>>>(
        inputs_1d, w_qs, w_kvs, w_qp, w_kvp, b_qs, b_kvs, b_qp, b_kvp);

    // 2) rotations / frames
    rot_kernel<<<Nn, 192>>>(rotation, translat, tpw, b_a2);

    // 3) scalar/point logits
    lgsp_kernel<<<dim3(6, 12, 12), 128>>>(mask);

    // 4) fused attention (captured by ncu as 4th launch)
    {
        const int smem = 26256 * (int)sizeof(float);
        cudaFuncSetAttribute(attn_fused_kernel, cudaFuncAttributeMaxDynamicSharedMemorySize, smem);
        attn_fused_kernel<<<Nn, 256, smem>>>(inputs_2d, w_a2);
    }

    pv_kernel<<<dim3(Nn / 64, Hh), 256>>>();
    local_kernel<<<Nn, 288>>>(rotation, translat);

    gemm_out_kernel<<<dim3(384 / 64, Nn / 64, 4), 256>>>(w_out);
    reduce_out_kernel<<<(Nn * 384 + 255) / 256, 256>>>(b_out, out);
}